// round 8
// baseline (speedup 1.0000x reference)
#include <cuda_runtime.h>

#define NBLK   10
#define NBATCH 2048
#define NCH    64
#define NSKIP  96
#define TILE   32
#define NCTA   (NBATCH/TILE)           /* 64 */
#define NCOLS  1023
#define CURP   68                      /* padded row stride for cur/del/z */
#define SSP    100                     /* padded row stride for skip/h */
#define NBUF   ((size_t)NBATCH*NCH*NCOLS)   /* 134086656 */

__device__ float g_currents[NBLK * NBATCH * NCH];

#define FMA4(acc, s, v) do { (acc)[0] += (s)*(v).x; (acc)[1] += (s)*(v).y; \
                             (acc)[2] += (s)*(v).z; (acc)[3] += (s)*(v).w; } while(0)

// ---------------------------------------------------------------------------
// Compute kernel: 64 CTAs x 256 threads. CTA owns 32 samples.
// Thread = (sp 0..15, tg 0..15): 2 samples x 4 channels register tile
// (same per-thread shape as the proven R1 layout; 2 warps/SMSP for issue).
// Weight smem is PHASE-SHARED: w0..w3 for f/g, then wrs+wst for res/skip.
// ---------------------------------------------------------------------------
__global__ __launch_bounds__(256, 1) void wn_compute(
    const float* __restrict__ x,   const float* __restrict__ buf,
    const float* __restrict__ inp_w, const float* __restrict__ inp_b,
    const float* __restrict__ fw0, const float* __restrict__ fw1, const float* __restrict__ fb,
    const float* __restrict__ gw0, const float* __restrict__ gw1, const float* __restrict__ gb,
    const float* __restrict__ rw,  const float* __restrict__ rb,
    const float* __restrict__ sw,  const float* __restrict__ sb,
    const float* __restrict__ h1w, const float* __restrict__ h1b,
    const float* __restrict__ h2w, const float* __restrict__ h2b,
    float* __restrict__ out)
{
    extern __shared__ float sm[];
    float* cur  = sm;                         // 32*68
    float* zs   = cur + TILE*CURP;            // 32*68 (x tile, then z)
    float* del  = zs  + TILE*CURP;            // 10*32*68 delayed taps
    float* wreg = del + NBLK*TILE*CURP;       // 16384 floats, phase-shared
    float* bia  = wreg + 16384;               // fb[64] gb[64] rb[64] sb[96]
    float* ssm  = bia + 288;                  // 32*100 skip sums
    float* hsm  = ssm + TILE*SSP;             // 32*100 hidden

    float* w0 = wreg;            // f/g phase: 4 transposed 64x64 matrices
    float* w1 = wreg + 4096;
    float* w2 = wreg + 8192;
    float* w3 = wreg + 12288;
    float* wrs = wreg;           // res/skip phase: res 64x64 + skip 64x96
    float* wst = wreg + 4096;

    const int tid   = threadIdx.x;
    const int bbase = blockIdx.x * TILE;
    const int sp = tid >> 4, tg = tid & 15;
    const int s0 = sp*2, s1 = s0+1, t0 = tg*4, ts = tg*6;

    // ---- x tile into zs scratch (32 x 32) ----
    for (int idx = tid; idx < TILE*32; idx += 256)
        zs[idx] = x[(bbase + (idx >> 5))*32 + (idx & 31)];

    // ---- preload all delayed taps: del[i][s][c] = buf[b, c, 2^i - 1] ----
    for (int idx = tid; idx < NBLK*TILE*NCH; idx += 256) {
        int i = idx >> 11;                   // / (32*64)
        int r = idx & 2047;
        int s = r >> 6, c = r & 63;
        int off = (1 << i) - 1;
        del[(i*TILE + s)*CURP + c] =
            buf[((size_t)(bbase + s)*NCH + c)*NCOLS + off];
    }
    __syncthreads();

    // ---- input projection: cur = x @ inp_w.T + inp_b ----
    {
        float a0[4], a1[4];
        #pragma unroll
        for (int j = 0; j < 4; ++j) { a0[j] = inp_b[t0+j]; a1[j] = a0[j]; }
        #pragma unroll 8
        for (int k = 0; k < 32; ++k) {
            float x0 = zs[s0*32+k], x1 = zs[s1*32+k];
            #pragma unroll
            for (int j = 0; j < 4; ++j) {
                float w = inp_w[(t0+j)*32 + k];
                a0[j] += x0*w; a1[j] += x1*w;
            }
        }
        #pragma unroll
        for (int j = 0; j < 4; ++j) {
            cur[s0*CURP + t0 + j] = a0[j];
            cur[s1*CURP + t0 + j] = a1[j];
        }
    }

    float ssum0[6], ssum1[6];
    #pragma unroll
    for (int j = 0; j < 6; ++j) { ssum0[j] = 0.f; ssum1[j] = 0.f; }

    for (int i = 0; i < NBLK; ++i) {
        __syncthreads();   // cur stable; prev-iter weight reads done

        // ---- phase 1 staging: w0..w3 (f/g weights, transposed) + biases ----
        {
            const float* srcs[4] = { fw0 + i*4096, fw1 + i*4096,
                                     gw0 + i*4096, gw1 + i*4096 };
            float* dsts[4] = { w0, w1, w2, w3 };
            #pragma unroll
            for (int mm = 0; mm < 4; ++mm) {
                const float* s = srcs[mm]; float* d = dsts[mm];
                #pragma unroll
                for (int it = 0; it < 4; ++it) {
                    int idx = it*256 + tid;           // 1024 float4 total
                    int q = idx >> 6, t = idx & 63;
                    float4 v = *(const float4*)(s + t*64 + q*4);
                    d[(4*q+0)*64+t] = v.x; d[(4*q+1)*64+t] = v.y;
                    d[(4*q+2)*64+t] = v.z; d[(4*q+3)*64+t] = v.w;
                }
            }
            if (tid < 64) {
                bia[tid]      = fb[i*64+tid];
                bia[64+tid]   = gb[i*64+tid];
                bia[128+tid]  = rb[i*64+tid];
            }
            if (tid >= 64 && tid < 160) bia[192+tid-64] = sb[i*NSKIP+tid-64];
        }
        __syncthreads();

        // ---- f/g GEMMs ----
        float f0[4], f1[4], g0[4], g1[4];
        #pragma unroll
        for (int j = 0; j < 4; ++j) {
            f0[j] = bia[t0+j];    f1[j] = f0[j];
            g0[j] = bia[64+t0+j]; g1[j] = g0[j];
        }
        const float* dle = del + i*TILE*CURP;
        #pragma unroll 8
        for (int k = 0; k < 64; ++k) {
            float d0 = dle[s0*CURP+k], d1 = dle[s1*CURP+k];
            float c0 = cur[s0*CURP+k], c1 = cur[s1*CURP+k];
            float4 wa = *(const float4*)(w0 + k*64 + t0);
            float4 wb = *(const float4*)(w1 + k*64 + t0);
            float4 wc = *(const float4*)(w2 + k*64 + t0);
            float4 wd = *(const float4*)(w3 + k*64 + t0);
            FMA4(f0, d0, wa); FMA4(f0, c0, wb);
            FMA4(f1, d1, wa); FMA4(f1, c1, wb);
            FMA4(g0, d0, wc); FMA4(g0, c0, wd);
            FMA4(g1, d1, wc); FMA4(g1, c1, wd);
        }

        // ---- z = tanh(f) * sigmoid(g) ----
        float z0[4], z1[4];
        #pragma unroll
        for (int j = 0; j < 4; ++j) {
            z0[j] = tanhf(f0[j]) * (1.f / (1.f + __expf(-g0[j])));
            z1[j] = tanhf(f1[j]) * (1.f / (1.f + __expf(-g1[j])));
        }
        *(float4*)(zs + s0*CURP + t0) = make_float4(z0[0],z0[1],z0[2],z0[3]);
        *(float4*)(zs + s1*CURP + t0) = make_float4(z1[0],z1[1],z1[2],z1[3]);
        __syncthreads();   // f/g weight reads done; z visible

        // ---- phase 2 staging: wrs + wst; snapshot cur -> g_currents ----
        {
            const float* s = rw + i*4096;
            #pragma unroll
            for (int it = 0; it < 4; ++it) {
                int idx = it*256 + tid;               // 1024 float4
                int q = idx >> 6, t = idx & 63;
                float4 v = *(const float4*)(s + t*64 + q*4);
                wrs[(4*q+0)*64+t] = v.x; wrs[(4*q+1)*64+t] = v.y;
                wrs[(4*q+2)*64+t] = v.z; wrs[(4*q+3)*64+t] = v.w;
            }
            const float* s2 = sw + i*NSKIP*NCH;       // [96][64] -> wst[64][96]
            #pragma unroll
            for (int it = 0; it < 6; ++it) {
                int idx = it*256 + tid;               // 1536 float4
                int q = idx / 96, t = idx - q*96;
                float4 v = *(const float4*)(s2 + t*64 + q*4);
                wst[(4*q+0)*96+t] = v.x; wst[(4*q+1)*96+t] = v.y;
                wst[(4*q+2)*96+t] = v.z; wst[(4*q+3)*96+t] = v.w;
            }
            // snapshot current entering block i (cur stable until update below)
            float4* dst = (float4*)(g_currents + (size_t)i*NBATCH*NCH
                                               + (size_t)bbase*NCH);
            #pragma unroll
            for (int it = 0; it < 2; ++it) {
                int idx = it*256 + tid;               // 512 float4 = 32*64
                int ss = idx >> 4, q = idx & 15;
                dst[idx] = *(const float4*)(cur + ss*CURP + q*4);
            }
        }
        __syncthreads();

        // ---- res + skip GEMMs ----
        float r0[4], r1[4];
        #pragma unroll
        for (int j = 0; j < 4; ++j) { r0[j] = bia[128+t0+j]; r1[j] = r0[j]; }
        #pragma unroll 8
        for (int k = 0; k < 64; ++k) {
            float zk0 = zs[s0*CURP+k], zk1 = zs[s1*CURP+k];
            float4 wv = *(const float4*)(wrs + k*64 + t0);
            FMA4(r0, zk0, wv); FMA4(r1, zk1, wv);
            const float* wsk = wst + k*96 + ts;
            #pragma unroll
            for (int j = 0; j < 6; ++j) {
                float w = wsk[j];
                ssum0[j] += zk0*w; ssum1[j] += zk1*w;
            }
        }
        #pragma unroll
        for (int j = 0; j < 6; ++j) {
            ssum0[j] += bia[192+ts+j];
            ssum1[j] += bia[192+ts+j];
        }

        // ---- residual update of current (owner-exclusive) ----
        {
            float4 c4 = *(float4*)(cur + s0*CURP + t0);
            c4.x += 0.3f*r0[0]; c4.y += 0.3f*r0[1];
            c4.z += 0.3f*r0[2]; c4.w += 0.3f*r0[3];
            *(float4*)(cur + s0*CURP + t0) = c4;
            float4 d4 = *(float4*)(cur + s1*CURP + t0);
            d4.x += 0.3f*r1[0]; d4.y += 0.3f*r1[1];
            d4.z += 0.3f*r1[2]; d4.w += 0.3f*r1[3];
            *(float4*)(cur + s1*CURP + t0) = d4;
        }
    }

    // ---- head ----
    __syncthreads();
    #pragma unroll
    for (int j = 0; j < 6; ++j) {
        ssm[s0*SSP + ts + j] = fmaxf(ssum0[j], 0.f);
        ssm[s1*SSP + ts + j] = fmaxf(ssum1[j], 0.f);
    }
    for (int idx = tid; idx < NSKIP*NSKIP; idx += 256) {   // h1w transposed
        int k = idx / 96, t = idx - k*96;
        wreg[idx] = h1w[t*96 + k];
    }
    __syncthreads();
    {
        float a0[6], a1[6];
        #pragma unroll
        for (int j = 0; j < 6; ++j) { a0[j] = h1b[ts+j]; a1[j] = a0[j]; }
        #pragma unroll 4
        for (int k = 0; k < 96; ++k) {
            float u0 = ssm[s0*SSP+k], u1 = ssm[s1*SSP+k];
            const float* wk = wreg + k*96 + ts;
            #pragma unroll
            for (int j = 0; j < 6; ++j) {
                float w = wk[j];
                a0[j] += u0*w; a1[j] += u1*w;
            }
        }
        #pragma unroll
        for (int j = 0; j < 6; ++j) {
            hsm[s0*SSP + ts + j] = fmaxf(a0[j], 0.f);
            hsm[s1*SSP + ts + j] = fmaxf(a1[j], 0.f);
        }
    }
    __syncthreads();
    if (tid < 64) {
        int s = tid >> 1, jj = tid & 1;
        float a = h2b[jj];
        #pragma unroll 4
        for (int k = 0; k < 96; ++k)
            a += hsm[s*SSP+k] * h2w[jj*96+k];
        out[(bbase+s)*2 + jj] = a;
    }
}

// ---------------------------------------------------------------------------
// Shift: dst[n] = src[n+1], fully coalesced (lane-interleaved float4).
// Warp owns 2048 contiguous floats: A[r] = f4[r*32 + lane], r = 0..15.
// Grid 16368 x 128 covers NBUF exactly (16368*8192 = 134086656).
// ---------------------------------------------------------------------------
__global__ __launch_bounds__(128) void wn_shift(const float* __restrict__ src,
                                                float* __restrict__ dst)
{
    const int warp = threadIdx.x >> 5;
    const unsigned lane = threadIdx.x & 31;
    const size_t base = (size_t)blockIdx.x*8192 + (size_t)warp*2048;  // floats
    const float4* s4 = (const float4*)(src + base);
    float4*       d4 = (float4*)(dst + base);

    float bnd = 0.f;
    if (lane == 31) {
        size_t g = base + 2048;
        bnd = src[g < NBUF ? g : NBUF - 1];   // clamp slot is an insertion col
    }
    float4 A[16];
    #pragma unroll
    for (int r = 0; r < 16; ++r) A[r] = s4[r*32 + lane];

    #pragma unroll
    for (int r = 0; r < 16; ++r) {
        float nd = __shfl_down_sync(0xffffffffu, A[r].x, 1);
        float n0 = (r < 15) ? __shfl_sync(0xffffffffu, A[r+1].x, 0) : bnd;
        float nxt = (lane == 31) ? n0 : nd;
        d4[r*32 + lane] = make_float4(A[r].y, A[r].z, A[r].w, nxt);
    }
}

// ---------------------------------------------------------------------------
// Scatter: overwrite the 10 insertion columns j = 2^(i+1)-2 with current_i.
// ---------------------------------------------------------------------------
__global__ __launch_bounds__(256) void wn_scatter(float* __restrict__ dst)
{
    int idx = blockIdx.x*blockDim.x + threadIdx.x;
    if (idx < NBLK*NBATCH*NCH) {
        int i = idx >> 17;                 // / (2048*64)
        int r = idx & ((1 << 17) - 1);     // b*64+c
        int j = (2 << i) - 2;              // 2^(i+1)-2
        dst[(size_t)r*NCOLS + j] = g_currents[idx];
    }
}

extern "C" void kernel_launch(void* const* d_in, const int* in_sizes, int n_in,
                              void* d_out, int out_size)
{
    const float* x     = (const float*)d_in[0];
    const float* buf   = (const float*)d_in[1];
    const float* inp_w = (const float*)d_in[2];
    const float* inp_b = (const float*)d_in[3];
    const float* fw0   = (const float*)d_in[4];
    const float* fw1   = (const float*)d_in[5];
    const float* fb    = (const float*)d_in[6];
    const float* gw0   = (const float*)d_in[7];
    const float* gw1   = (const float*)d_in[8];
    const float* gb    = (const float*)d_in[9];
    const float* rw    = (const float*)d_in[10];
    const float* rb    = (const float*)d_in[11];
    const float* sw    = (const float*)d_in[12];
    const float* sb    = (const float*)d_in[13];
    const float* h1w   = (const float*)d_in[14];
    const float* h1b   = (const float*)d_in[15];
    const float* h2w   = (const float*)d_in[16];
    const float* h2b   = (const float*)d_in[17];

    float* out  = (float*)d_out;            // (2048, 2)
    float* nbuf = out + NBATCH*2;           // (2048, 64, 1023)

    // lazy one-time creation (first call = correctness run, before capture)
    static cudaStream_t s2 = nullptr;
    static cudaEvent_t ev_fork = nullptr, ev_join = nullptr;
    if (!s2) {
        int lo, hi;
        cudaDeviceGetStreamPriorityRange(&lo, &hi);   // lo = LEAST priority
        cudaStreamCreateWithPriority(&s2, cudaStreamNonBlocking, lo);
        cudaEventCreateWithFlags(&ev_fork, cudaEventDisableTiming);
        cudaEventCreateWithFlags(&ev_join, cudaEventDisableTiming);
    }

    const int smem_bytes =
        (TILE*CURP*2 + NBLK*TILE*CURP + 16384 + 288 + 2*TILE*SSP)
        * (int)sizeof(float);               // 196736 B
    cudaFuncSetAttribute(wn_compute, cudaFuncAttributeMaxDynamicSharedMemorySize,
                         smem_bytes);

    // fork: compute launched FIRST (grabs its SM slots); shift fills the rest
    cudaEventRecord(ev_fork, 0);
    cudaStreamWaitEvent(s2, ev_fork, 0);

    wn_compute<<<NCTA, 256, smem_bytes>>>(
        x, buf, inp_w, inp_b, fw0, fw1, fb, gw0, gw1, gb,
        rw, rb, sw, sb, h1w, h1b, h2w, h2b, out);

    wn_shift<<<16368, 128, 0, s2>>>(buf, nbuf);
    cudaEventRecord(ev_join, s2);

    // join: scatter needs both compute (g_currents) and shift (nbuf)
    cudaStreamWaitEvent(0, ev_join, 0);
    wn_scatter<<<(NBLK*NBATCH*NCH)/256, 256>>>(nbuf);
}